// round 14
// baseline (speedup 1.0000x reference)
#include <cuda_runtime.h>
#include <cuda_fp16.h>
#include <cstdint>

#define NN 100000
#define NE 1600000
#define FH 128
#define FO 40

// ======================= device scratch (no allocs allowed) =======================
__device__ int   g_deg[NN];
__device__ float g_dinv[NN];
__device__ float g_rdinv[NN];
__device__ int   g_rowoff[NN + 1];
__device__ int   g_cursor[NN];
__device__ int   g_csr[NE];
__device__ int   g_bsum[128];
__device__ int   g_boff[128];

// prescaled (x*dinv) fp16 activation planes
__device__ __half g_F0[2][(size_t)NN * FH];
__device__ __half g_F1[(size_t)NN * FH];
__device__ __half g_F2[(size_t)NN * FH];   // only for the final layer now
// hidden weights: exact f16 hi/lo split of W^T  [n=128][k=384]
__device__ __half g_Wh[6 * 128 * 384];
__device__ __half g_Wl[6 * 128 * 384];
// final weights: exact f16 hi/lo split of Wl^T padded to [n=64][k=384]
__device__ __half g_WFh[64 * 384];
__device__ __half g_WFl[64 * 384];

// ======================= helpers =======================
__device__ __forceinline__ uint32_t smem_u32(const void* p) {
    uint32_t a;
    asm("{ .reg .u64 t; cvta.to.shared.u64 t, %1; cvt.u32.u64 %0, t; }" : "=r"(a) : "l"(p));
    return a;
}

#define SWZ(off) ((off) ^ (((off) >> 3) & 0x70))

__device__ __forceinline__ void ldmx4(uint32_t* r, uint32_t addr) {
    asm volatile("ldmatrix.sync.aligned.m8n8.x4.shared.b16 {%0,%1,%2,%3}, [%4];"
                 : "=r"(r[0]), "=r"(r[1]), "=r"(r[2]), "=r"(r[3]) : "r"(addr));
}

__device__ __forceinline__ void mma_f16(float* d, const uint32_t* a, const uint32_t* b) {
    asm volatile(
        "mma.sync.aligned.m16n8k16.row.col.f32.f16.f16.f32 "
        "{%0,%1,%2,%3}, {%4,%5,%6,%7}, {%8,%9}, {%0,%1,%2,%3};"
        : "+f"(d[0]), "+f"(d[1]), "+f"(d[2]), "+f"(d[3])
        : "r"(a[0]), "r"(a[1]), "r"(a[2]), "r"(a[3]), "r"(b[0]), "r"(b[1]));
}

__device__ __forceinline__ void cpa16(uint32_t saddr, const void* g, bool pred) {
    asm volatile("cp.async.cg.shared.global [%0], [%1], 16, %2;"
                 :: "r"(saddr), "l"(g), "r"(pred ? 16 : 0) : "memory");
}
#define CP_COMMIT() asm volatile("cp.async.commit_group;" ::: "memory")
#define CP_WAIT(n)  asm volatile("cp.async.wait_group %0;" :: "n"(n) : "memory")

__device__ __forceinline__ float2 h2f2(uint32_t u) {
    __half2 h = *reinterpret_cast<__half2*>(&u);
    return __half22float2(h);
}
__device__ __forceinline__ uint32_t f2h2(float a, float b) {
    __half2 h = __floats2half2_rn(a, b);
    return *reinterpret_cast<uint32_t*>(&h);
}

// ======================= graph preprocessing =======================
__global__ void k_hist(const int* __restrict__ dst) {
    int e = blockIdx.x * blockDim.x + threadIdx.x;
    if (e < NE) atomicAdd(&g_deg[dst[e]], 1);
}

__global__ void __launch_bounds__(1024) k_scanA() {
    __shared__ int wsum[32];
    int t = threadIdx.x, lane = t & 31, wp = t >> 5;
    int i = blockIdx.x * 1024 + t;
    int v = (i < NN) ? g_deg[i] : 0;
    int x = v;
    #pragma unroll
    for (int o = 1; o < 32; o <<= 1) {
        int y = __shfl_up_sync(0xffffffffu, x, o);
        if (lane >= o) x += y;
    }
    if (lane == 31) wsum[wp] = x;
    __syncthreads();
    if (wp == 0) {
        int s = wsum[lane];
        #pragma unroll
        for (int o = 1; o < 32; o <<= 1) {
            int y = __shfl_up_sync(0xffffffffu, s, o);
            if (lane >= o) s += y;
        }
        wsum[lane] = s;
    }
    __syncthreads();
    int off = (wp ? wsum[wp - 1] : 0);
    if (i < NN) g_rowoff[i] = off + x - v;
    if (t == 1023) g_bsum[blockIdx.x] = wsum[31];
}

__global__ void k_scanB(int nb) {
    __shared__ int sh[4];
    int t = threadIdx.x, lane = t & 31, wp = t >> 5;
    int v = (t < nb) ? g_bsum[t] : 0;
    int x = v;
    #pragma unroll
    for (int o = 1; o < 32; o <<= 1) {
        int y = __shfl_up_sync(0xffffffffu, x, o);
        if (lane >= o) x += y;
    }
    if (lane == 31) sh[wp] = x;
    __syncthreads();
    int add = 0;
    for (int w = 0; w < wp; ++w) add += sh[w];
    if (t < 128) g_boff[t] = add + x - v;
}

__global__ void k_scanC() {
    int i = blockIdx.x * blockDim.x + threadIdx.x;
    if (i < NN) {
        int r = g_rowoff[i] + g_boff[i >> 10];
        g_rowoff[i] = r;
        g_cursor[i] = r;
        int d = g_deg[i];
        float df = (float)(d > 1 ? d : 1);
        g_dinv[i] = rsqrtf(df);
        g_rdinv[i] = sqrtf(df);
    }
    if (i == 0) g_rowoff[NN] = NE;
}

__global__ void k_scatter(const int* __restrict__ src, const int* __restrict__ dst) {
    int e = blockIdx.x * blockDim.x + threadIdx.x;
    if (e < NE) {
        int p = atomicAdd(&g_cursor[dst[e]], 1);
        g_csr[p] = src[e];
    }
}

// ======================= input conversion =======================
__global__ void k_featsplit(const float* __restrict__ f) {
    size_t i = ((size_t)blockIdx.x * blockDim.x + threadIdx.x) * 4;
    if (i >= (size_t)NN * FH) return;
    int row = (int)(i >> 7);
    float dv = g_dinv[row];
    float4 v = *(const float4*)(f + i);
    uint2 q;
    q.x = f2h2(v.x * dv, v.y * dv);
    q.y = f2h2(v.z * dv, v.w * dv);
    *(uint2*)(&g_F0[0][i]) = q;
}

__global__ void k_prep_w(const float* __restrict__ W0, const float* __restrict__ Wh) {
    int i = blockIdx.x * blockDim.x + threadIdx.x;
    if (i >= 6 * 384 * 128) return;
    int l = i / (384 * 128);
    int r = i % (384 * 128);
    int k = r / 128, n = r % 128;
    const float* W = (l == 0) ? W0 : (Wh + (size_t)(l - 1) * 384 * 128);
    float v = W[(size_t)k * 128 + n];
    __half h = __float2half_rn(v);
    float lo = v - __half2float(h);
    size_t o = (size_t)l * 128 * 384 + (size_t)n * 384 + k;
    g_Wh[o] = h;
    g_Wl[o] = __float2half_rn(lo);
}

__global__ void k_prep_wf(const float* __restrict__ Wl) {
    int i = blockIdx.x * blockDim.x + threadIdx.x;
    if (i >= 64 * 384) return;
    int n = i / 384, k = i % 384;
    float v = (n < FO) ? Wl[(size_t)k * FO + n] : 0.f;
    __half h = __float2half_rn(v);
    float lo = v - __half2float(h);
    g_WFh[i] = h;
    g_WFl[i] = __float2half_rn(lo);
}

// ======================= SpMM: warp-per-node CSR gather, fp16 in/out ============
template <int MODE>
__global__ void __launch_bounds__(256) k_spmm(
    const __half* __restrict__ Y,
    const __half* __restrict__ X0,
    __half* __restrict__ o) {
    int w = (blockIdx.x * blockDim.x + threadIdx.x) >> 5;
    int lane = threadIdx.x & 31;
    if (w >= NN) return;
    int beg = g_rowoff[w];
    int end = g_rowoff[w + 1];
    const size_t lo4 = (size_t)(lane * 4);
    float a0 = 0.f, a1 = 0.f, a2 = 0.f, a3 = 0.f;
    int i = beg;
    for (; i + 4 <= end; i += 4) {
        int s0 = g_csr[i], s1 = g_csr[i + 1], s2 = g_csr[i + 2], s3 = g_csr[i + 3];
        uint2 u0 = *(const uint2*)(Y + (size_t)s0 * FH + lo4);
        uint2 u1 = *(const uint2*)(Y + (size_t)s1 * FH + lo4);
        uint2 u2 = *(const uint2*)(Y + (size_t)s2 * FH + lo4);
        uint2 u3 = *(const uint2*)(Y + (size_t)s3 * FH + lo4);
        float2 f;
        f = h2f2(u0.x); a0 += f.x; a1 += f.y;
        f = h2f2(u0.y); a2 += f.x; a3 += f.y;
        f = h2f2(u1.x); a0 += f.x; a1 += f.y;
        f = h2f2(u1.y); a2 += f.x; a3 += f.y;
        f = h2f2(u2.x); a0 += f.x; a1 += f.y;
        f = h2f2(u2.y); a2 += f.x; a3 += f.y;
        f = h2f2(u3.x); a0 += f.x; a1 += f.y;
        f = h2f2(u3.y); a2 += f.x; a3 += f.y;
    }
    for (; i < end; ++i) {
        int s0 = g_csr[i];
        uint2 u0 = *(const uint2*)(Y + (size_t)s0 * FH + lo4);
        float2 f;
        f = h2f2(u0.x); a0 += f.x; a1 += f.y;
        f = h2f2(u0.y); a2 += f.x; a3 += f.y;
    }
    float dv = g_dinv[w];
    float dv2 = dv * dv;
    float p0, p1, p2, p3;
    if (MODE == 1) {
        float m = -dv2;
        p0 = m * a0; p1 = m * a1; p2 = m * a2; p3 = m * a3;
    } else {
        uint2 xq = *(const uint2*)(X0 + (size_t)w * FH + lo4);
        float2 x0 = h2f2(xq.x), x1 = h2f2(xq.y);
        float m = -2.f * dv2;
        p0 = fmaf(m, a0, -x0.x);
        p1 = fmaf(m, a1, -x0.y);
        p2 = fmaf(m, a2, -x1.x);
        p3 = fmaf(m, a3, -x1.y);
    }
    uint2 q;
    q.x = f2h2(p0, p1);
    q.y = f2h2(p2, p3);
    *(uint2*)(o + (size_t)w * FH + lo4) = q;
}

// ======================= fused GEMM: in-kernel X2 gather + mma ==================
// Chunk order {4,5,0,1,2,3}: X2 chunks (kc4->stage0 A, kc5->stage1 A) are computed
// by a gather prologue (STS) and consumed FIRST; remaining chunks stream via
// cp.async exactly as the champion. Zero extra smem; 2 CTAs/SM preserved.
#define GS_A   0
#define GS_BHI 16384
#define GS_BLO 32768
#define GS_ST  49152
#define GM_SMEM_SZ (2 * GS_ST)

__global__ void __launch_bounds__(512, 2) k_gemm_fused(
    const __half* __restrict__ x0,
    const float* __restrict__ bias,
    const __half* __restrict__ wh, const __half* __restrict__ wl,
    __half* __restrict__ outp) {
    extern __shared__ char smem_raw[];
    __shared__ float s_bias[128];
    uint32_t sb0 = smem_u32(smem_raw);
    uint32_t sb = (sb0 + 1023u) & ~1023u;
    char* smc = smem_raw + (sb - sb0);

    const int tid = threadIdx.x, lane = tid & 31, wid = tid >> 5;
    const int wm = wid >> 2, wn = wid & 3;
    const int rowBase = blockIdx.x * 128;
    if (tid < 128) s_bias[tid] = bias[tid];

    // start weight chunk for kc4 moving while we gather
    {
        #pragma unroll
        for (int t = 0; t < 2; ++t) {
            int idx = tid + t * 512;
            int n = idx >> 3, j = idx & 7;
            uint32_t sw = SWZ((uint32_t)(n * 128 + j * 16));
            cpa16(sb + GS_BHI + sw, wh + (size_t)n * 384 + 4 * 64 + j * 8, true);
            cpa16(sb + GS_BLO + sw, wl + (size_t)n * 384 + 4 * 64 + j * 8, true);
        }
        CP_COMMIT();
    }

    // ---- gather prologue: X2 tile -> stage0 A (chunk0) / stage1 A (chunk1) ----
    {
        const size_t lo4 = (size_t)(lane * 4);
        // lane covers features lane*4..+3; chunk = lane>>4, in-chunk byte = (lane&15)*8
        const int chunk = lane >> 4;
        char* dstBase = smc + (chunk ? GS_ST : 0) + GS_A;
        const uint32_t fo8 = (uint32_t)((lane & 15) * 8);
        #pragma unroll 1
        for (int rr = 0; rr < 8; ++rr) {
            int r = wid * 8 + rr;            // local row 0..127
            int row = rowBase + r;
            if (row < NN) {
                int beg = g_rowoff[row], end = g_rowoff[row + 1];
                float a0 = 0.f, a1 = 0.f, a2 = 0.f, a3 = 0.f;
                int i = beg;
                for (; i + 2 <= end; i += 2) {
                    int s0 = g_csr[i], s1 = g_csr[i + 1];
                    uint2 u0 = *(const uint2*)(g_F1 + (size_t)s0 * FH + lo4);
                    uint2 u1 = *(const uint2*)(g_F1 + (size_t)s1 * FH + lo4);
                    float2 f;
                    f = h2f2(u0.x); a0 += f.x; a1 += f.y;
                    f = h2f2(u0.y); a2 += f.x; a3 += f.y;
                    f = h2f2(u1.x); a0 += f.x; a1 += f.y;
                    f = h2f2(u1.y); a2 += f.x; a3 += f.y;
                }
                if (i < end) {
                    int s0 = g_csr[i];
                    uint2 u0 = *(const uint2*)(g_F1 + (size_t)s0 * FH + lo4);
                    float2 f;
                    f = h2f2(u0.x); a0 += f.x; a1 += f.y;
                    f = h2f2(u0.y); a2 += f.x; a3 += f.y;
                }
                float dv = g_dinv[row];
                float m = -2.f * dv * dv;
                uint2 xq = *(const uint2*)(x0 + (size_t)row * FH + lo4);
                float2 xa = h2f2(xq.x), xb = h2f2(xq.y);
                uint2 q;
                q.x = f2h2(fmaf(m, a0, -xa.x), fmaf(m, a1, -xa.y));
                q.y = f2h2(fmaf(m, a2, -xb.x), fmaf(m, a3, -xb.y));
                uint32_t sw = SWZ((uint32_t)(r * 128) + fo8);
                *(uint2*)(dstBase + sw) = q;
            }
        }
    }

    const __half* Ap[2] = {x0, g_F1};   // bases for kc 0..3

    float acc[2][4][4];
    #pragma unroll
    for (int a = 0; a < 2; ++a)
        #pragma unroll
        for (int b = 0; b < 4; ++b)
            #pragma unroll
            for (int c = 0; c < 4; ++c) acc[a][b][c] = 0.f;

    const int lrow = lane & 7, seg = lane >> 3;
    const int kcs[6] = {4, 5, 0, 1, 2, 3};

    auto load_chunk = [&](uint32_t st, int kc) {
        // B always
        #pragma unroll
        for (int t = 0; t < 2; ++t) {
            int idx = tid + t * 512;
            int n = idx >> 3, j = idx & 7;
            uint32_t sw = SWZ((uint32_t)(n * 128 + j * 16));
            cpa16(st + GS_BHI + sw, wh + (size_t)n * 384 + kc * 64 + j * 8, true);
            cpa16(st + GS_BLO + sw, wl + (size_t)n * 384 + kc * 64 + j * 8, true);
        }
        // A only for streamed chunks
        if (kc < 4) {
            const int coff = (kc & 1) * 64;
            const __half* __restrict__ ap = Ap[kc >> 1];
            #pragma unroll
            for (int t = 0; t < 2; ++t) {
                int idx = tid + t * 512;
                int r = idx >> 3, j = idx & 7;
                int row = rowBase + r;
                bool ok = row < NN;
                int rowc = ok ? row : (NN - 1);
                uint32_t sw = SWZ((uint32_t)(r * 128 + j * 16));
                cpa16(st + GS_A + sw, ap + (size_t)rowc * FH + coff + j * 8, ok);
            }
        }
    };

    #pragma unroll 1
    for (int ii = 0; ii < 6; ++ii) {
        if (ii < 5) {
            load_chunk(sb + (((ii + 1) & 1) ? GS_ST : 0), kcs[ii + 1]);
            CP_COMMIT();
            CP_WAIT(1);
        } else {
            CP_WAIT(0);
        }
        __syncthreads();

        const uint32_t st = sb + ((ii & 1) ? GS_ST : 0);
        #pragma unroll
        for (int kt = 0; kt < 4; ++kt) {
            uint32_t Af[2][4], Bhf[2][4], Blf[2][4];
            #pragma unroll
            for (int mt = 0; mt < 2; ++mt) {
                int m = wm * 32 + mt * 16 + (seg & 1) * 8 + lrow;
                int kb = kt * 32 + (seg >> 1) * 16;
                uint32_t sw = SWZ((uint32_t)(m * 128 + kb));
                ldmx4(Af[mt], st + GS_A + sw);
            }
            #pragma unroll
            for (int ntp = 0; ntp < 2; ++ntp) {
                int n = wn * 32 + ntp * 16 + (seg >> 1) * 8 + lrow;
                int kb = kt * 32 + (seg & 1) * 16;
                uint32_t sw = SWZ((uint32_t)(n * 128 + kb));
                ldmx4(Bhf[ntp], st + GS_BHI + sw);
                ldmx4(Blf[ntp], st + GS_BLO + sw);
            }
            #pragma unroll
            for (int mt = 0; mt < 2; ++mt)
                #pragma unroll
                for (int ntp = 0; ntp < 2; ++ntp)
                    #pragma unroll
                    for (int sub = 0; sub < 2; ++sub) {
                        int nj = ntp * 2 + sub;
                        mma_f16(acc[mt][nj], Af[mt], &Bhf[ntp][sub * 2]);
                        mma_f16(acc[mt][nj], Af[mt], &Blf[ntp][sub * 2]);
                    }
        }
        __syncthreads();
    }

    // ---- epilogue: p = relu(acc*rdinv + b)*dinv; write fp16 ----
    #pragma unroll
    for (int mt = 0; mt < 2; ++mt) {
        #pragma unroll
        for (int rp = 0; rp < 2; ++rp) {
            int row = rowBase + wm * 32 + mt * 16 + (lane >> 2) + rp * 8;
            if (row < NN) {
                float dv = g_dinv[row], rd = g_rdinv[row];
                #pragma unroll
                for (int nj = 0; nj < 4; ++nj) {
                    int col = wn * 32 + nj * 8 + (lane & 3) * 2;
                    float bz0 = s_bias[col], bz1 = s_bias[col + 1];
                    float p0 = fmaxf(fmaf(acc[mt][nj][rp * 2 + 0], rd, bz0), 0.f) * dv;
                    float p1 = fmaxf(fmaf(acc[mt][nj][rp * 2 + 1], rd, bz1), 0.f) * dv;
                    *(uint32_t*)(outp + (size_t)row * FH + col) = f2h2(p0, p1);
                }
            }
        }
    }
}

// ======================= final layer: mma GEMM, N padded to 64 ==================
#define GF_A   0
#define GF_BHI 16384
#define GF_BLO 24576
#define GF_ST  32768
#define GF_SMEM_SZ (2 * GF_ST)

__global__ void __launch_bounds__(256, 3) k_gemm_final(
    const __half* __restrict__ x0,
    const float* __restrict__ bias,
    float* __restrict__ out) {
    extern __shared__ char smem_raw[];
    __shared__ float s_bias[64];
    uint32_t sb0 = smem_u32(smem_raw);
    uint32_t sb = (sb0 + 1023u) & ~1023u;

    const int tid = threadIdx.x, lane = tid & 31, wid = tid >> 5;
    const int wm = wid >> 1, wn = wid & 1;
    const int rowBase = blockIdx.x * 128;
    if (tid < 64) s_bias[tid] = (tid < FO) ? bias[tid] : 0.f;
    __syncthreads();

    const __half* Ap[3] = {x0, g_F1, g_F2};

    float acc[2][4][4];
    #pragma unroll
    for (int a = 0; a < 2; ++a)
        #pragma unroll
        for (int b = 0; b < 4; ++b)
            #pragma unroll
            for (int c = 0; c < 4; ++c) acc[a][b][c] = 0.f;

    const int lrow = lane & 7, seg = lane >> 3;

    auto load_chunk = [&](uint32_t st, int kc) {
        const int coff = (kc & 1) * 64;
        const __half* __restrict__ ap = Ap[kc >> 1];
        #pragma unroll
        for (int t = 0; t < 4; ++t) {
            int idx = tid + t * 256;
            int r = idx >> 3, j = idx & 7;
            int row = rowBase + r;
            bool ok = row < NN;
            int rowc = ok ? row : (NN - 1);
            uint32_t sw = SWZ((uint32_t)(r * 128 + j * 16));
            cpa16(st + GF_A + sw, ap + (size_t)rowc * FH + coff + j * 8, ok);
        }
        #pragma unroll
        for (int t = 0; t < 2; ++t) {
            int idx = tid + t * 256;
            int n = idx >> 3, j = idx & 7;
            uint32_t sw = SWZ((uint32_t)(n * 128 + j * 16));
            cpa16(st + GF_BHI + sw, g_WFh + (size_t)n * 384 + kc * 64 + j * 8, true);
            cpa16(st + GF_BLO + sw, g_WFl + (size_t)n * 384 + kc * 64 + j * 8, true);
        }
    };

    load_chunk(sb, 0);
    CP_COMMIT();

    #pragma unroll 1
    for (int kc = 0; kc < 6; ++kc) {
        if (kc < 5) {
            load_chunk(sb + (((kc + 1) & 1) ? GF_ST : 0), kc + 1);
            CP_COMMIT();
            CP_WAIT(1);
        } else {
            CP_WAIT(0);
        }
        __syncthreads();

        const uint32_t st = sb + ((kc & 1) ? GF_ST : 0);
        #pragma unroll
        for (int kt = 0; kt < 4; ++kt) {
            uint32_t Af[2][4], Bhf[2][4], Blf[2][4];
            #pragma unroll
            for (int mt = 0; mt < 2; ++mt) {
                int m = wm * 32 + mt * 16 + (seg & 1) * 8 + lrow;
                int kb = kt * 32 + (seg >> 1) * 16;
                uint32_t sw = SWZ((uint32_t)(m * 128 + kb));
                ldmx4(Af[mt], st + GF_A + sw);
            }
            #pragma unroll
            for (int ntp = 0; ntp < 2; ++ntp) {
                int n = wn * 32 + ntp * 16 + (seg >> 1) * 8 + lrow;
                int kb = kt * 32 + (seg & 1) * 16;
                uint32_t sw = SWZ((uint32_t)(n * 128 + kb));
                ldmx4(Bhf[ntp], st + GF_BHI + sw);
                ldmx4(Blf[ntp], st + GF_BLO + sw);
            }
            #pragma unroll
            for (int mt = 0; mt < 2; ++mt)
                #pragma unroll
                for (int ntp = 0; ntp < 2; ++ntp)
                    #pragma unroll
                    for (int sub = 0; sub < 2; ++sub) {
                        int nj = ntp * 2 + sub;
                        mma_f16(acc[mt][nj], Af[mt], &Bhf[ntp][sub * 2]);
                        mma_f16(acc[mt][nj], Af[mt], &Blf[ntp][sub * 2]);
                    }
        }
        __syncthreads();
    }

    #pragma unroll
    for (int mt = 0; mt < 2; ++mt) {
        #pragma unroll
        for (int rp = 0; rp < 2; ++rp) {
            int row = rowBase + wm * 32 + mt * 16 + (lane >> 2) + rp * 8;
            if (row < NN) {
                float rd = g_rdinv[row];
                #pragma unroll
                for (int nj = 0; nj < 4; ++nj) {
                    int col = wn * 32 + nj * 8 + (lane & 3) * 2;
                    if (col < FO) {
                        float bz0 = s_bias[col], bz1 = s_bias[col + 1];
                        float p0 = fmaxf(fmaf(acc[mt][nj][rp * 2 + 0], rd, bz0), 0.f);
                        float p1 = fmaxf(fmaf(acc[mt][nj][rp * 2 + 1], rd, bz1), 0.f);
                        *(float2*)(out + (size_t)row * FO + col) = make_float2(p0, p1);
                    }
                }
            }
        }
    }
}

// ======================= host launcher =======================
extern "C" void kernel_launch(void* const* d_in, const int* in_sizes, int n_in,
                              void* d_out, int out_size) {
    const float* feat = (const float*)d_in[0];
    const int*   src  = (const int*)d_in[1];
    const int*   dst  = (const int*)d_in[2];
    const float* W0   = (const float*)d_in[3];
    const float* b0   = (const float*)d_in[4];
    const float* Wh_  = (const float*)d_in[5];
    const float* bh   = (const float*)d_in[6];
    const float* Wl_  = (const float*)d_in[7];
    const float* bl   = (const float*)d_in[8];
    float* out = (float*)d_out;

    __half *F0, *F1, *F2, *Wh, *Wl;
    int* degp;
    cudaGetSymbolAddress((void**)&F0, g_F0);
    cudaGetSymbolAddress((void**)&F1, g_F1);
    cudaGetSymbolAddress((void**)&F2, g_F2);
    cudaGetSymbolAddress((void**)&Wh, g_Wh);
    cudaGetSymbolAddress((void**)&Wl, g_Wl);
    cudaGetSymbolAddress((void**)&degp, g_deg);

    cudaFuncSetAttribute(k_gemm_fused, cudaFuncAttributeMaxDynamicSharedMemorySize,
                         GM_SMEM_SZ + 1024);
    cudaFuncSetAttribute(k_gemm_final, cudaFuncAttributeMaxDynamicSharedMemorySize,
                         GF_SMEM_SZ + 1024);

    const int TPB = 256;
    const int nodeBlocks = (NN + TPB - 1) / TPB;
    const int edgeBlocks = (NE + TPB - 1) / TPB;
    const int scanBlocks = (NN + 1023) / 1024;   // 98

    // preprocessing
    cudaMemsetAsync(degp, 0, NN * sizeof(int));
    k_hist<<<edgeBlocks, TPB>>>(dst);
    k_scanA<<<scanBlocks, 1024>>>();
    k_scanB<<<1, 128>>>(scanBlocks);
    k_scanC<<<nodeBlocks, TPB>>>();
    k_scatter<<<edgeBlocks, TPB>>>(src, dst);

    // input conversion
    k_featsplit<<<(NN * FH / 4 + TPB - 1) / TPB, TPB>>>(feat);
    k_prep_w<<<(6 * 384 * 128 + TPB - 1) / TPB, TPB>>>(W0, Wh_);
    k_prep_wf<<<(64 * 384 + TPB - 1) / TPB, TPB>>>(Wl_);

    const size_t SL = (size_t)NN * FH;
    const int spmmBlocks = (NN * 32 + TPB - 1) / TPB;
    const int tileBlocks = (NN + 127) / 128;

    int cur = 0;
    for (int l = 0; l < 7; ++l) {
        const __half* F0c = F0 + (size_t)cur * SL;
        k_spmm<1><<<spmmBlocks, TPB>>>(F0c, nullptr, F1);
        if (l < 6) {
            const float* bias = (l == 0) ? b0 : (bh + (size_t)(l - 1) * 128);
            int nxt = 1 - cur;
            k_gemm_fused<<<tileBlocks, 512, GM_SMEM_SZ + 1024>>>(
                F0c, bias,
                Wh + (size_t)l * 128 * 384, Wl + (size_t)l * 128 * 384,
                F0 + (size_t)nxt * SL);
            cur = nxt;
        } else {
            k_spmm<2><<<spmmBlocks, TPB>>>(F1, F0c, F2);
            k_gemm_final<<<tileBlocks, 256, GF_SMEM_SZ + 1024>>>(F0c, bl, out);
        }
    }
}

// round 15
// speedup vs baseline: 1.0323x; 1.0323x over previous
#include <cuda_runtime.h>
#include <cuda_fp16.h>
#include <cstdint>

#define NN 100000
#define NE 1600000
#define FH 128
#define FO 40

// ======================= device scratch (no allocs allowed) =======================
__device__ int   g_deg[NN];
__device__ float g_dinv[NN];
__device__ float g_rdinv[NN];
__device__ int   g_rowoff[NN + 1];
__device__ int   g_cursor[NN];
__device__ int   g_csr[NE];
__device__ int   g_bsum[128];
__device__ int   g_boff[128];

// prescaled (x*dinv) fp16 activation planes
__device__ __half g_F0[2][(size_t)NN * FH];
__device__ __half g_F1[(size_t)NN * FH];
__device__ __half g_F2[(size_t)NN * FH];
// hidden weights: exact f16 hi/lo split of W^T  [n=128][k=384]
__device__ __half g_Wh[6 * 128 * 384];
__device__ __half g_Wl[6 * 128 * 384];
// final weights: exact f16 hi/lo split of Wl^T padded to [n=64][k=384]
__device__ __half g_WFh[64 * 384];
__device__ __half g_WFl[64 * 384];

// ======================= helpers =======================
__device__ __forceinline__ uint32_t smem_u32(const void* p) {
    uint32_t a;
    asm("{ .reg .u64 t; cvta.to.shared.u64 t, %1; cvt.u32.u64 %0, t; }" : "=r"(a) : "l"(p));
    return a;
}

#define SWZ(off) ((off) ^ (((off) >> 3) & 0x70))

__device__ __forceinline__ void ldmx4(uint32_t* r, uint32_t addr) {
    asm volatile("ldmatrix.sync.aligned.m8n8.x4.shared.b16 {%0,%1,%2,%3}, [%4];"
                 : "=r"(r[0]), "=r"(r[1]), "=r"(r[2]), "=r"(r[3]) : "r"(addr));
}

__device__ __forceinline__ void mma_f16(float* d, const uint32_t* a, const uint32_t* b) {
    asm volatile(
        "mma.sync.aligned.m16n8k16.row.col.f32.f16.f16.f32 "
        "{%0,%1,%2,%3}, {%4,%5,%6,%7}, {%8,%9}, {%0,%1,%2,%3};"
        : "+f"(d[0]), "+f"(d[1]), "+f"(d[2]), "+f"(d[3])
        : "r"(a[0]), "r"(a[1]), "r"(a[2]), "r"(a[3]), "r"(b[0]), "r"(b[1]));
}

__device__ __forceinline__ void cpa16(uint32_t saddr, const void* g, bool pred) {
    asm volatile("cp.async.cg.shared.global [%0], [%1], 16, %2;"
                 :: "r"(saddr), "l"(g), "r"(pred ? 16 : 0) : "memory");
}
#define CP_COMMIT() asm volatile("cp.async.commit_group;" ::: "memory")
#define CP_WAIT(n)  asm volatile("cp.async.wait_group %0;" :: "n"(n) : "memory")

__device__ __forceinline__ float2 h2f2(uint32_t u) {
    __half2 h = *reinterpret_cast<__half2*>(&u);
    return __half22float2(h);
}
__device__ __forceinline__ uint32_t f2h2(float a, float b) {
    __half2 h = __floats2half2_rn(a, b);
    return *reinterpret_cast<uint32_t*>(&h);
}

// ======================= graph preprocessing =======================
__global__ void k_hist(const int* __restrict__ dst) {
    int e = blockIdx.x * blockDim.x + threadIdx.x;
    if (e < NE) atomicAdd(&g_deg[dst[e]], 1);
}

__global__ void __launch_bounds__(1024) k_scanA() {
    __shared__ int wsum[32];
    int t = threadIdx.x, lane = t & 31, wp = t >> 5;
    int i = blockIdx.x * 1024 + t;
    int v = (i < NN) ? g_deg[i] : 0;
    int x = v;
    #pragma unroll
    for (int o = 1; o < 32; o <<= 1) {
        int y = __shfl_up_sync(0xffffffffu, x, o);
        if (lane >= o) x += y;
    }
    if (lane == 31) wsum[wp] = x;
    __syncthreads();
    if (wp == 0) {
        int s = wsum[lane];
        #pragma unroll
        for (int o = 1; o < 32; o <<= 1) {
            int y = __shfl_up_sync(0xffffffffu, s, o);
            if (lane >= o) s += y;
        }
        wsum[lane] = s;
    }
    __syncthreads();
    int off = (wp ? wsum[wp - 1] : 0);
    if (i < NN) g_rowoff[i] = off + x - v;
    if (t == 1023) g_bsum[blockIdx.x] = wsum[31];
}

__global__ void k_scanB(int nb) {
    __shared__ int sh[4];
    int t = threadIdx.x, lane = t & 31, wp = t >> 5;
    int v = (t < nb) ? g_bsum[t] : 0;
    int x = v;
    #pragma unroll
    for (int o = 1; o < 32; o <<= 1) {
        int y = __shfl_up_sync(0xffffffffu, x, o);
        if (lane >= o) x += y;
    }
    if (lane == 31) sh[wp] = x;
    __syncthreads();
    int add = 0;
    for (int w = 0; w < wp; ++w) add += sh[w];
    if (t < 128) g_boff[t] = add + x - v;
}

__global__ void k_scanC() {
    int i = blockIdx.x * blockDim.x + threadIdx.x;
    if (i < NN) {
        int r = g_rowoff[i] + g_boff[i >> 10];
        g_rowoff[i] = r;
        g_cursor[i] = r;
        int d = g_deg[i];
        float df = (float)(d > 1 ? d : 1);
        g_dinv[i] = rsqrtf(df);
        g_rdinv[i] = sqrtf(df);
    }
    if (i == 0) g_rowoff[NN] = NE;
}

__global__ void k_scatter(const int* __restrict__ src, const int* __restrict__ dst) {
    int e = blockIdx.x * blockDim.x + threadIdx.x;
    if (e < NE) {
        int p = atomicAdd(&g_cursor[dst[e]], 1);
        g_csr[p] = src[e];
    }
}

// ======================= merged input conversion =======================
// blocks [0, FS_BLK): featsplit; [FS_BLK, FS_BLK+PW_BLK): prep_w; rest: prep_wf
#define FS_BLK 12500
#define PW_BLK 1152
#define PF_BLK 96
__global__ void k_prep(const float* __restrict__ f,
                       const float* __restrict__ W0, const float* __restrict__ Wh,
                       const float* __restrict__ Wl) {
    int b = blockIdx.x;
    if (b < FS_BLK) {
        size_t i = ((size_t)b * blockDim.x + threadIdx.x) * 4;
        if (i >= (size_t)NN * FH) return;
        int row = (int)(i >> 7);
        float dv = g_dinv[row];
        float4 v = *(const float4*)(f + i);
        uint2 q;
        q.x = f2h2(v.x * dv, v.y * dv);
        q.y = f2h2(v.z * dv, v.w * dv);
        *(uint2*)(&g_F0[0][i]) = q;
    } else if (b < FS_BLK + PW_BLK) {
        int i = (b - FS_BLK) * blockDim.x + threadIdx.x;
        if (i >= 6 * 384 * 128) return;
        int l = i / (384 * 128);
        int r = i % (384 * 128);
        int k = r / 128, n = r % 128;
        const float* W = (l == 0) ? W0 : (Wh + (size_t)(l - 1) * 384 * 128);
        float v = W[(size_t)k * 128 + n];
        __half h = __float2half_rn(v);
        float lo = v - __half2float(h);
        size_t o = (size_t)l * 128 * 384 + (size_t)n * 384 + k;
        g_Wh[o] = h;
        g_Wl[o] = __float2half_rn(lo);
    } else {
        int i = (b - FS_BLK - PW_BLK) * blockDim.x + threadIdx.x;
        if (i >= 64 * 384) return;
        int n = i / 384, k = i % 384;
        float v = (n < FO) ? Wl[(size_t)k * FO + n] : 0.f;
        __half h = __float2half_rn(v);
        float lo = v - __half2float(h);
        g_WFh[i] = h;
        g_WFl[i] = __float2half_rn(lo);
    }
}

// ======================= SpMM: warp-per-node CSR gather, fp16 in/out ============
// (exact R13 champion)
template <int MODE>
__global__ void __launch_bounds__(256) k_spmm(
    const __half* __restrict__ Y,
    const __half* __restrict__ X0,
    __half* __restrict__ o) {
    int w = (blockIdx.x * blockDim.x + threadIdx.x) >> 5;
    int lane = threadIdx.x & 31;
    if (w >= NN) return;
    int beg = g_rowoff[w];
    int end = g_rowoff[w + 1];
    const size_t lo4 = (size_t)(lane * 4);
    float a0 = 0.f, a1 = 0.f, a2 = 0.f, a3 = 0.f;
    int i = beg;
    for (; i + 4 <= end; i += 4) {
        int s0 = g_csr[i], s1 = g_csr[i + 1], s2 = g_csr[i + 2], s3 = g_csr[i + 3];
        uint2 u0 = *(const uint2*)(Y + (size_t)s0 * FH + lo4);
        uint2 u1 = *(const uint2*)(Y + (size_t)s1 * FH + lo4);
        uint2 u2 = *(const uint2*)(Y + (size_t)s2 * FH + lo4);
        uint2 u3 = *(const uint2*)(Y + (size_t)s3 * FH + lo4);
        float2 f;
        f = h2f2(u0.x); a0 += f.x; a1 += f.y;
        f = h2f2(u0.y); a2 += f.x; a3 += f.y;
        f = h2f2(u1.x); a0 += f.x; a1 += f.y;
        f = h2f2(u1.y); a2 += f.x; a3 += f.y;
        f = h2f2(u2.x); a0 += f.x; a1 += f.y;
        f = h2f2(u2.y); a2 += f.x; a3 += f.y;
        f = h2f2(u3.x); a0 += f.x; a1 += f.y;
        f = h2f2(u3.y); a2 += f.x; a3 += f.y;
    }
    for (; i < end; ++i) {
        int s0 = g_csr[i];
        uint2 u0 = *(const uint2*)(Y + (size_t)s0 * FH + lo4);
        float2 f;
        f = h2f2(u0.x); a0 += f.x; a1 += f.y;
        f = h2f2(u0.y); a2 += f.x; a3 += f.y;
    }
    float dv = g_dinv[w];
    float dv2 = dv * dv;
    float p0, p1, p2, p3;
    if (MODE == 1) {
        float m = -dv2;
        p0 = m * a0; p1 = m * a1; p2 = m * a2; p3 = m * a3;
    } else {
        uint2 xq = *(const uint2*)(X0 + (size_t)w * FH + lo4);
        float2 x0 = h2f2(xq.x), x1 = h2f2(xq.y);
        float m = -2.f * dv2;
        p0 = fmaf(m, a0, -x0.x);
        p1 = fmaf(m, a1, -x0.y);
        p2 = fmaf(m, a2, -x1.x);
        p3 = fmaf(m, a3, -x1.y);
    }
    uint2 q;
    q.x = f2h2(p0, p1);
    q.y = f2h2(p2, p3);
    *(uint2*)(o + (size_t)w * FH + lo4) = q;
}

// ======================= persistent pipelined mma.sync GEMM =====================
// (R13 body wrapped in a persistent tile loop; grid = 296 = 148 SM x 2 CTA)
#define GS_A   0
#define GS_BHI 16384
#define GS_BLO 32768
#define GS_ST  49152
#define GM_SMEM_SZ (2 * GS_ST)
#define GM_GRID 296

__global__ void __launch_bounds__(512, 2) k_gemm_mma(
    const __half* __restrict__ x0,
    const float* __restrict__ bias,
    const __half* __restrict__ wh, const __half* __restrict__ wl,
    __half* __restrict__ outp, int nTiles) {
    extern __shared__ char smem_raw[];
    __shared__ float s_bias[128];
    uint32_t sb0 = smem_u32(smem_raw);
    uint32_t sb = (sb0 + 1023u) & ~1023u;

    const int tid = threadIdx.x, lane = tid & 31, wid = tid >> 5;
    const int wm = wid >> 2, wn = wid & 3;
    if (tid < 128) s_bias[tid] = bias[tid];
    __syncthreads();

    const __half* Ap[3] = {x0, g_F1, g_F2};
    const int lrow = lane & 7, seg = lane >> 3;

    int rowBase;
    auto load_chunk = [&](uint32_t st, int kc) {
        const int coff = (kc & 1) * 64;
        const __half* __restrict__ ap = Ap[kc >> 1];
        #pragma unroll
        for (int t = 0; t < 2; ++t) {
            int idx = tid + t * 512;
            int r = idx >> 3, j = idx & 7;
            int row = rowBase + r;
            bool ok = row < NN;
            int rowc = ok ? row : (NN - 1);
            uint32_t sw = SWZ((uint32_t)(r * 128 + j * 16));
            cpa16(st + GS_A + sw, ap + (size_t)rowc * FH + coff + j * 8, ok);
        }
        #pragma unroll
        for (int t = 0; t < 2; ++t) {
            int idx = tid + t * 512;
            int n = idx >> 3, j = idx & 7;
            uint32_t sw = SWZ((uint32_t)(n * 128 + j * 16));
            cpa16(st + GS_BHI + sw, wh + (size_t)n * 384 + kc * 64 + j * 8, true);
            cpa16(st + GS_BLO + sw, wl + (size_t)n * 384 + kc * 64 + j * 8, true);
        }
    };

    #pragma unroll 1
    for (int tile = blockIdx.x; tile < nTiles; tile += GM_GRID) {
        rowBase = tile * 128;

        float acc[2][4][4];
        #pragma unroll
        for (int a = 0; a < 2; ++a)
            #pragma unroll
            for (int b = 0; b < 4; ++b)
                #pragma unroll
                for (int c = 0; c < 4; ++c) acc[a][b][c] = 0.f;

        load_chunk(sb, 0);
        CP_COMMIT();

        #pragma unroll 1
        for (int kc = 0; kc < 6; ++kc) {
            if (kc < 5) {
                load_chunk(sb + (((kc + 1) & 1) ? GS_ST : 0), kc + 1);
                CP_COMMIT();
                CP_WAIT(1);
            } else {
                CP_WAIT(0);
            }
            __syncthreads();

            const uint32_t st = sb + ((kc & 1) ? GS_ST : 0);
            #pragma unroll
            for (int kt = 0; kt < 4; ++kt) {
                uint32_t Af[2][4], Bhf[2][4], Blf[2][4];
                #pragma unroll
                for (int mt = 0; mt < 2; ++mt) {
                    int m = wm * 32 + mt * 16 + (seg & 1) * 8 + lrow;
                    int kb = kt * 32 + (seg >> 1) * 16;
                    uint32_t sw = SWZ((uint32_t)(m * 128 + kb));
                    ldmx4(Af[mt], st + GS_A + sw);
                }
                #pragma unroll
                for (int ntp = 0; ntp < 2; ++ntp) {
                    int n = wn * 32 + ntp * 16 + (seg >> 1) * 8 + lrow;
                    int kb = kt * 32 + (seg & 1) * 16;
                    uint32_t sw = SWZ((uint32_t)(n * 128 + kb));
                    ldmx4(Bhf[ntp], st + GS_BHI + sw);
                    ldmx4(Blf[ntp], st + GS_BLO + sw);
                }
                #pragma unroll
                for (int mt = 0; mt < 2; ++mt)
                    #pragma unroll
                    for (int ntp = 0; ntp < 2; ++ntp)
                        #pragma unroll
                        for (int sub = 0; sub < 2; ++sub) {
                            int nj = ntp * 2 + sub;
                            mma_f16(acc[mt][nj], Af[mt], &Bhf[ntp][sub * 2]);
                            mma_f16(acc[mt][nj], Af[mt], &Blf[ntp][sub * 2]);
                        }
            }
            __syncthreads();
        }

        // epilogue: p = relu(acc*rdinv + b)*dinv; write fp16
        #pragma unroll
        for (int mt = 0; mt < 2; ++mt) {
            #pragma unroll
            for (int rp = 0; rp < 2; ++rp) {
                int row = rowBase + wm * 32 + mt * 16 + (lane >> 2) + rp * 8;
                if (row < NN) {
                    float dv = g_dinv[row], rd = g_rdinv[row];
                    #pragma unroll
                    for (int nj = 0; nj < 4; ++nj) {
                        int col = wn * 32 + nj * 8 + (lane & 3) * 2;
                        float bz0 = s_bias[col], bz1 = s_bias[col + 1];
                        float p0 = fmaxf(fmaf(acc[mt][nj][rp * 2 + 0], rd, bz0), 0.f) * dv;
                        float p1 = fmaxf(fmaf(acc[mt][nj][rp * 2 + 1], rd, bz1), 0.f) * dv;
                        *(uint32_t*)(outp + (size_t)row * FH + col) = f2h2(p0, p1);
                    }
                }
            }
        }
    }
}

// ======================= final layer: persistent mma GEMM, N padded to 64 ========
#define GF_A   0
#define GF_BHI 16384
#define GF_BLO 24576
#define GF_ST  32768
#define GF_SMEM_SZ (2 * GF_ST)
#define GF_GRID 444

__global__ void __launch_bounds__(256, 3) k_gemm_final(
    const __half* __restrict__ x0,
    const float* __restrict__ bias,
    float* __restrict__ out, int nTiles) {
    extern __shared__ char smem_raw[];
    __shared__ float s_bias[64];
    uint32_t sb0 = smem_u32(smem_raw);
    uint32_t sb = (sb0 + 1023u) & ~1023u;

    const int tid = threadIdx.x, lane = tid & 31, wid = tid >> 5;
    const int wm = wid >> 1, wn = wid & 1;
    if (tid < 64) s_bias[tid] = (tid < FO) ? bias[tid] : 0.f;
    __syncthreads();

    const __half* Ap[3] = {x0, g_F1, g_F2};
    const int lrow = lane & 7, seg = lane >> 3;

    int rowBase;
    auto load_chunk = [&](uint32_t st, int kc) {
        const int coff = (kc & 1) * 64;
        const __half* __restrict__ ap = Ap[kc >> 1];
        #pragma unroll
        for (int t = 0; t < 4; ++t) {
            int idx = tid + t * 256;
            int r = idx >> 3, j = idx & 7;
            int row = rowBase + r;
            bool ok = row < NN;
            int rowc = ok ? row : (NN - 1);
            uint32_t sw = SWZ((uint32_t)(r * 128 + j * 16));
            cpa16(st + GF_A + sw, ap + (size_t)rowc * FH + coff + j * 8, ok);
        }
        #pragma unroll
        for (int t = 0; t < 2; ++t) {
            int idx = tid + t * 256;
            int n = idx >> 3, j = idx & 7;
            uint32_t sw = SWZ((uint32_t)(n * 128 + j * 16));
            cpa16(st + GF_BHI + sw, g_WFh + (size_t)n * 384 + kc * 64 + j * 8, true);
            cpa16(st + GF_BLO + sw, g_WFl + (size_t)n * 384 + kc * 64 + j * 8, true);
        }
    };

    #pragma unroll 1
    for (int tile = blockIdx.x; tile < nTiles; tile += GF_GRID) {
        rowBase = tile * 128;

        float acc[2][4][4];
        #pragma unroll
        for (int a = 0; a < 2; ++a)
            #pragma unroll
            for (int b = 0; b < 4; ++b)
                #pragma unroll
                for (int c = 0; c < 4; ++c) acc[a][b][c] = 0.f;

        load_chunk(sb, 0);
        CP_COMMIT();

        #pragma unroll 1
        for (int kc = 0; kc < 6; ++kc) {
            if (kc < 5) {
                load_chunk(sb + (((kc + 1) & 1) ? GF_ST : 0), kc + 1);
                CP_COMMIT();
                CP_WAIT(1);
            } else {
                CP_WAIT(0);
            }
            __syncthreads();

            const uint32_t st = sb + ((kc & 1) ? GF_ST : 0);
            #pragma unroll
            for (int kt = 0; kt < 4; ++kt) {
                uint32_t Af[2][4], Bhf[2][4], Blf[2][4];
                #pragma unroll
                for (int mt = 0; mt < 2; ++mt) {
                    int m = wm * 32 + mt * 16 + (seg & 1) * 8 + lrow;
                    int kb = kt * 32 + (seg >> 1) * 16;
                    uint32_t sw = SWZ((uint32_t)(m * 128 + kb));
                    ldmx4(Af[mt], st + GF_A + sw);
                }
                #pragma unroll
                for (int ntp = 0; ntp < 2; ++ntp) {
                    int n = wn * 32 + ntp * 16 + (seg >> 1) * 8 + lrow;
                    int kb = kt * 32 + (seg & 1) * 16;
                    uint32_t sw = SWZ((uint32_t)(n * 128 + kb));
                    ldmx4(Bhf[ntp], st + GF_BHI + sw);
                    ldmx4(Blf[ntp], st + GF_BLO + sw);
                }
                #pragma unroll
                for (int mt = 0; mt < 2; ++mt)
                    #pragma unroll
                    for (int ntp = 0; ntp < 2; ++ntp)
                        #pragma unroll
                        for (int sub = 0; sub < 2; ++sub) {
                            int nj = ntp * 2 + sub;
                            mma_f16(acc[mt][nj], Af[mt], &Bhf[ntp][sub * 2]);
                            mma_f16(acc[mt][nj], Af[mt], &Blf[ntp][sub * 2]);
                        }
            }
            __syncthreads();
        }

        #pragma unroll
        for (int mt = 0; mt < 2; ++mt) {
            #pragma unroll
            for (int rp = 0; rp < 2; ++rp) {
                int row = rowBase + wm * 32 + mt * 16 + (lane >> 2) + rp * 8;
                if (row < NN) {
                    float rd = g_rdinv[row];
                    #pragma unroll
                    for (int nj = 0; nj < 4; ++nj) {
                        int col = wn * 32 + nj * 8 + (lane & 3) * 2;
                        if (col < FO) {
                            float bz0 = s_bias[col], bz1 = s_bias[col + 1];
                            float p0 = fmaxf(fmaf(acc[mt][nj][rp * 2 + 0], rd, bz0), 0.f);
                            float p1 = fmaxf(fmaf(acc[mt][nj][rp * 2 + 1], rd, bz1), 0.f);
                            *(float2*)(out + (size_t)row * FO + col) = make_float2(p0, p1);
                        }
                    }
                }
            }
        }
    }
}

// ======================= host launcher =======================
extern "C" void kernel_launch(void* const* d_in, const int* in_sizes, int n_in,
                              void* d_out, int out_size) {
    const float* feat = (const float*)d_in[0];
    const int*   src  = (const int*)d_in[1];
    const int*   dst  = (const int*)d_in[2];
    const float* W0   = (const float*)d_in[3];
    const float* b0   = (const float*)d_in[4];
    const float* Wh_  = (const float*)d_in[5];
    const float* bh   = (const float*)d_in[6];
    const float* Wl_  = (const float*)d_in[7];
    const float* bl   = (const float*)d_in[8];
    float* out = (float*)d_out;

    __half *F0, *F1, *F2, *Wh, *Wl;
    int* degp;
    cudaGetSymbolAddress((void**)&F0, g_F0);
    cudaGetSymbolAddress((void**)&F1, g_F1);
    cudaGetSymbolAddress((void**)&F2, g_F2);
    cudaGetSymbolAddress((void**)&Wh, g_Wh);
    cudaGetSymbolAddress((void**)&Wl, g_Wl);
    cudaGetSymbolAddress((void**)&degp, g_deg);

    cudaFuncSetAttribute(k_gemm_mma, cudaFuncAttributeMaxDynamicSharedMemorySize,
                         GM_SMEM_SZ + 1024);
    cudaFuncSetAttribute(k_gemm_final, cudaFuncAttributeMaxDynamicSharedMemorySize,
                         GF_SMEM_SZ + 1024);

    const int TPB = 256;
    const int nodeBlocks = (NN + TPB - 1) / TPB;
    const int edgeBlocks = (NE + TPB - 1) / TPB;
    const int scanBlocks = (NN + 1023) / 1024;   // 98

    // preprocessing
    cudaMemsetAsync(degp, 0, NN * sizeof(int));
    k_hist<<<edgeBlocks, TPB>>>(dst);
    k_scanA<<<scanBlocks, 1024>>>();
    k_scanB<<<1, 128>>>(scanBlocks);
    k_scanC<<<nodeBlocks, TPB>>>();
    k_scatter<<<edgeBlocks, TPB>>>(src, dst);

    // merged input conversion (featsplit | prep_w | prep_wf)
    k_prep<<<FS_BLK + PW_BLK + PF_BLK, TPB>>>(feat, W0, Wh_, Wl_);

    const size_t SL = (size_t)NN * FH;
    const int spmmBlocks = (NN * 32 + TPB - 1) / TPB;
    const int tileBlocks = (NN + 127) / 128;   // 782

    int cur = 0;
    for (int l = 0; l < 7; ++l) {
        const __half* F0c = F0 + (size_t)cur * SL;
        k_spmm<1><<<spmmBlocks, TPB>>>(F0c, nullptr, F1);
        k_spmm<2><<<spmmBlocks, TPB>>>(F1, F0c, F2);
        if (l < 6) {
            const float* bias = (l == 0) ? b0 : (bh + (size_t)(l - 1) * 128);
            int nxt = 1 - cur;
            k_gemm_mma<<<GM_GRID, 512, GM_SMEM_SZ + 1024>>>(
                F0c, bias,
                Wh + (size_t)l * 128 * 384, Wl + (size_t)l * 128 * 384,
                F0 + (size_t)nxt * SL, tileBlocks);
            cur = nxt;
        } else {
            k_gemm_final<<<GF_GRID, 256, GF_SMEM_SZ + 1024>>>(F0c, bl, out, tileBlocks);
        }
    }
}

// round 16
// speedup vs baseline: 1.0623x; 1.0291x over previous
#include <cuda_runtime.h>
#include <cuda_fp16.h>
#include <cstdint>

#define NN 100000
#define NE 1600000
#define FH 128
#define FO 40

// ======================= device scratch (no allocs allowed) =======================
__device__ int   g_deg[NN];
__device__ float g_dinv[NN];
__device__ float g_rdinv[NN];
__device__ int   g_rowoff[NN + 1];
__device__ int   g_cursor[NN];
__device__ int   g_csr[NE];
__device__ int   g_bsum[128];
__device__ int   g_boff[128];

// prescaled (x*dinv) fp16 activation planes
__device__ __half g_F0[2][(size_t)NN * FH];
__device__ __half g_F1[(size_t)NN * FH];
__device__ __half g_F2[(size_t)NN * FH];
// hidden weights: exact f16 hi/lo split of W^T  [n=128][k=384]
__device__ __half g_Wh[6 * 128 * 384];
__device__ __half g_Wl[6 * 128 * 384];
// final weights: exact f16 hi/lo split of Wl^T padded to [n=64][k=384]
__device__ __half g_WFh[64 * 384];
__device__ __half g_WFl[64 * 384];

// ======================= helpers =======================
__device__ __forceinline__ uint32_t smem_u32(const void* p) {
    uint32_t a;
    asm("{ .reg .u64 t; cvta.to.shared.u64 t, %1; cvt.u32.u64 %0, t; }" : "=r"(a) : "l"(p));
    return a;
}

#define SWZ(off) ((off) ^ (((off) >> 3) & 0x70))

__device__ __forceinline__ void ldmx4(uint32_t* r, uint32_t addr) {
    asm volatile("ldmatrix.sync.aligned.m8n8.x4.shared.b16 {%0,%1,%2,%3}, [%4];"
                 : "=r"(r[0]), "=r"(r[1]), "=r"(r[2]), "=r"(r[3]) : "r"(addr));
}

__device__ __forceinline__ void mma_f16(float* d, const uint32_t* a, const uint32_t* b) {
    asm volatile(
        "mma.sync.aligned.m16n8k16.row.col.f32.f16.f16.f32 "
        "{%0,%1,%2,%3}, {%4,%5,%6,%7}, {%8,%9}, {%0,%1,%2,%3};"
        : "+f"(d[0]), "+f"(d[1]), "+f"(d[2]), "+f"(d[3])
        : "r"(a[0]), "r"(a[1]), "r"(a[2]), "r"(a[3]), "r"(b[0]), "r"(b[1]));
}

__device__ __forceinline__ void cpa16(uint32_t saddr, const void* g, bool pred) {
    asm volatile("cp.async.cg.shared.global [%0], [%1], 16, %2;"
                 :: "r"(saddr), "l"(g), "r"(pred ? 16 : 0) : "memory");
}
#define CP_COMMIT() asm volatile("cp.async.commit_group;" ::: "memory")
#define CP_WAIT(n)  asm volatile("cp.async.wait_group %0;" :: "n"(n) : "memory")

__device__ __forceinline__ float2 h2f2(uint32_t u) {
    __half2 h = *reinterpret_cast<__half2*>(&u);
    return __half22float2(h);
}
__device__ __forceinline__ uint32_t f2h2(float a, float b) {
    __half2 h = __floats2half2_rn(a, b);
    return *reinterpret_cast<uint32_t*>(&h);
}

// ======================= graph preprocessing =======================
__global__ void k_hist(const int* __restrict__ dst) {
    int e = blockIdx.x * blockDim.x + threadIdx.x;
    if (e < NE) atomicAdd(&g_deg[dst[e]], 1);
}

__global__ void __launch_bounds__(1024) k_scanA() {
    __shared__ int wsum[32];
    int t = threadIdx.x, lane = t & 31, wp = t >> 5;
    int i = blockIdx.x * 1024 + t;
    int v = (i < NN) ? g_deg[i] : 0;
    int x = v;
    #pragma unroll
    for (int o = 1; o < 32; o <<= 1) {
        int y = __shfl_up_sync(0xffffffffu, x, o);
        if (lane >= o) x += y;
    }
    if (lane == 31) wsum[wp] = x;
    __syncthreads();
    if (wp == 0) {
        int s = wsum[lane];
        #pragma unroll
        for (int o = 1; o < 32; o <<= 1) {
            int y = __shfl_up_sync(0xffffffffu, s, o);
            if (lane >= o) s += y;
        }
        wsum[lane] = s;
    }
    __syncthreads();
    int off = (wp ? wsum[wp - 1] : 0);
    if (i < NN) g_rowoff[i] = off + x - v;
    if (t == 1023) g_bsum[blockIdx.x] = wsum[31];
}

__global__ void k_scanB(int nb) {
    __shared__ int sh[4];
    int t = threadIdx.x, lane = t & 31, wp = t >> 5;
    int v = (t < nb) ? g_bsum[t] : 0;
    int x = v;
    #pragma unroll
    for (int o = 1; o < 32; o <<= 1) {
        int y = __shfl_up_sync(0xffffffffu, x, o);
        if (lane >= o) x += y;
    }
    if (lane == 31) sh[wp] = x;
    __syncthreads();
    int add = 0;
    for (int w = 0; w < wp; ++w) add += sh[w];
    if (t < 128) g_boff[t] = add + x - v;
}

__global__ void k_scanC() {
    int i = blockIdx.x * blockDim.x + threadIdx.x;
    if (i < NN) {
        int r = g_rowoff[i] + g_boff[i >> 10];
        g_rowoff[i] = r;
        g_cursor[i] = r;
        int d = g_deg[i];
        float df = (float)(d > 1 ? d : 1);
        g_dinv[i] = rsqrtf(df);
        g_rdinv[i] = sqrtf(df);
    }
    if (i == 0) g_rowoff[NN] = NE;
}

__global__ void k_scatter(const int* __restrict__ src, const int* __restrict__ dst) {
    int e = blockIdx.x * blockDim.x + threadIdx.x;
    if (e < NE) {
        int p = atomicAdd(&g_cursor[dst[e]], 1);
        g_csr[p] = src[e];
    }
}

// ======================= merged input conversion =======================
// blocks [0, FS_BLK): featsplit; [FS_BLK, FS_BLK+PW_BLK): prep_w; rest: prep_wf
#define FS_BLK 12500
#define PW_BLK 1152
#define PF_BLK 96
__global__ void k_prep(const float* __restrict__ f,
                       const float* __restrict__ W0, const float* __restrict__ Wh,
                       const float* __restrict__ Wl) {
    int b = blockIdx.x;
    if (b < FS_BLK) {
        size_t i = ((size_t)b * blockDim.x + threadIdx.x) * 4;
        if (i >= (size_t)NN * FH) return;
        int row = (int)(i >> 7);
        float dv = g_dinv[row];
        float4 v = *(const float4*)(f + i);
        uint2 q;
        q.x = f2h2(v.x * dv, v.y * dv);
        q.y = f2h2(v.z * dv, v.w * dv);
        *(uint2*)(&g_F0[0][i]) = q;
    } else if (b < FS_BLK + PW_BLK) {
        int i = (b - FS_BLK) * blockDim.x + threadIdx.x;
        if (i >= 6 * 384 * 128) return;
        int l = i / (384 * 128);
        int r = i % (384 * 128);
        int k = r / 128, n = r % 128;
        const float* W = (l == 0) ? W0 : (Wh + (size_t)(l - 1) * 384 * 128);
        float v = W[(size_t)k * 128 + n];
        __half h = __float2half_rn(v);
        float lo = v - __half2float(h);
        size_t o = (size_t)l * 128 * 384 + (size_t)n * 384 + k;
        g_Wh[o] = h;
        g_Wl[o] = __float2half_rn(lo);
    } else {
        int i = (b - FS_BLK - PW_BLK) * blockDim.x + threadIdx.x;
        if (i >= 64 * 384) return;
        int n = i / 384, k = i % 384;
        float v = (n < FO) ? Wl[(size_t)k * FO + n] : 0.f;
        __half h = __float2half_rn(v);
        float lo = v - __half2float(h);
        g_WFh[i] = h;
        g_WFl[i] = __float2half_rn(lo);
    }
}

// ======================= SpMM: warp-per-node CSR gather, fp16 in/out ============
// (exact R13 champion)
template <int MODE>
__global__ void __launch_bounds__(256) k_spmm(
    const __half* __restrict__ Y,
    const __half* __restrict__ X0,
    __half* __restrict__ o) {
    int w = (blockIdx.x * blockDim.x + threadIdx.x) >> 5;
    int lane = threadIdx.x & 31;
    if (w >= NN) return;
    int beg = g_rowoff[w];
    int end = g_rowoff[w + 1];
    const size_t lo4 = (size_t)(lane * 4);
    float a0 = 0.f, a1 = 0.f, a2 = 0.f, a3 = 0.f;
    int i = beg;
    for (; i + 4 <= end; i += 4) {
        int s0 = g_csr[i], s1 = g_csr[i + 1], s2 = g_csr[i + 2], s3 = g_csr[i + 3];
        uint2 u0 = *(const uint2*)(Y + (size_t)s0 * FH + lo4);
        uint2 u1 = *(const uint2*)(Y + (size_t)s1 * FH + lo4);
        uint2 u2 = *(const uint2*)(Y + (size_t)s2 * FH + lo4);
        uint2 u3 = *(const uint2*)(Y + (size_t)s3 * FH + lo4);
        float2 f;
        f = h2f2(u0.x); a0 += f.x; a1 += f.y;
        f = h2f2(u0.y); a2 += f.x; a3 += f.y;
        f = h2f2(u1.x); a0 += f.x; a1 += f.y;
        f = h2f2(u1.y); a2 += f.x; a3 += f.y;
        f = h2f2(u2.x); a0 += f.x; a1 += f.y;
        f = h2f2(u2.y); a2 += f.x; a3 += f.y;
        f = h2f2(u3.x); a0 += f.x; a1 += f.y;
        f = h2f2(u3.y); a2 += f.x; a3 += f.y;
    }
    for (; i < end; ++i) {
        int s0 = g_csr[i];
        uint2 u0 = *(const uint2*)(Y + (size_t)s0 * FH + lo4);
        float2 f;
        f = h2f2(u0.x); a0 += f.x; a1 += f.y;
        f = h2f2(u0.y); a2 += f.x; a3 += f.y;
    }
    float dv = g_dinv[w];
    float dv2 = dv * dv;
    float p0, p1, p2, p3;
    if (MODE == 1) {
        float m = -dv2;
        p0 = m * a0; p1 = m * a1; p2 = m * a2; p3 = m * a3;
    } else {
        uint2 xq = *(const uint2*)(X0 + (size_t)w * FH + lo4);
        float2 x0 = h2f2(xq.x), x1 = h2f2(xq.y);
        float m = -2.f * dv2;
        p0 = fmaf(m, a0, -x0.x);
        p1 = fmaf(m, a1, -x0.y);
        p2 = fmaf(m, a2, -x1.x);
        p3 = fmaf(m, a3, -x1.y);
    }
    uint2 q;
    q.x = f2h2(p0, p1);
    q.y = f2h2(p2, p3);
    *(uint2*)(o + (size_t)w * FH + lo4) = q;
}

// ======================= pipelined mma.sync GEMM (exact R13 champion) ===========
#define GS_A   0
#define GS_BHI 16384
#define GS_BLO 32768
#define GS_ST  49152
#define GM_SMEM_SZ (2 * GS_ST)

__global__ void __launch_bounds__(512, 2) k_gemm_mma(
    const __half* __restrict__ x0,
    const float* __restrict__ bias,
    const __half* __restrict__ wh, const __half* __restrict__ wl,
    __half* __restrict__ outp) {
    extern __shared__ char smem_raw[];
    __shared__ float s_bias[128];
    uint32_t sb0 = smem_u32(smem_raw);
    uint32_t sb = (sb0 + 1023u) & ~1023u;

    const int tid = threadIdx.x, lane = tid & 31, wid = tid >> 5;
    const int wm = wid >> 2, wn = wid & 3;
    const int rowBase = blockIdx.x * 128;
    if (tid < 128) s_bias[tid] = bias[tid];
    __syncthreads();

    const __half* Ap[3] = {x0, g_F1, g_F2};

    float acc[2][4][4];
    #pragma unroll
    for (int a = 0; a < 2; ++a)
        #pragma unroll
        for (int b = 0; b < 4; ++b)
            #pragma unroll
            for (int c = 0; c < 4; ++c) acc[a][b][c] = 0.f;

    const int lrow = lane & 7, seg = lane >> 3;

    auto load_chunk = [&](uint32_t st, int kc) {
        const int coff = (kc & 1) * 64;
        const __half* __restrict__ ap = Ap[kc >> 1];
        #pragma unroll
        for (int t = 0; t < 2; ++t) {
            int idx = tid + t * 512;
            int r = idx >> 3, j = idx & 7;
            int row = rowBase + r;
            bool ok = row < NN;
            int rowc = ok ? row : (NN - 1);
            uint32_t sw = SWZ((uint32_t)(r * 128 + j * 16));
            cpa16(st + GS_A + sw, ap + (size_t)rowc * FH + coff + j * 8, ok);
        }
        #pragma unroll
        for (int t = 0; t < 2; ++t) {
            int idx = tid + t * 512;
            int n = idx >> 3, j = idx & 7;
            uint32_t sw = SWZ((uint32_t)(n * 128 + j * 16));
            cpa16(st + GS_BHI + sw, wh + (size_t)n * 384 + kc * 64 + j * 8, true);
            cpa16(st + GS_BLO + sw, wl + (size_t)n * 384 + kc * 64 + j * 8, true);
        }
    };

    load_chunk(sb, 0);
    CP_COMMIT();

    #pragma unroll 1
    for (int kc = 0; kc < 6; ++kc) {
        if (kc < 5) {
            load_chunk(sb + (((kc + 1) & 1) ? GS_ST : 0), kc + 1);
            CP_COMMIT();
            CP_WAIT(1);
        } else {
            CP_WAIT(0);
        }
        __syncthreads();

        const uint32_t st = sb + ((kc & 1) ? GS_ST : 0);
        #pragma unroll
        for (int kt = 0; kt < 4; ++kt) {
            uint32_t Af[2][4], Bhf[2][4], Blf[2][4];
            #pragma unroll
            for (int mt = 0; mt < 2; ++mt) {
                int m = wm * 32 + mt * 16 + (seg & 1) * 8 + lrow;
                int kb = kt * 32 + (seg >> 1) * 16;
                uint32_t sw = SWZ((uint32_t)(m * 128 + kb));
                ldmx4(Af[mt], st + GS_A + sw);
            }
            #pragma unroll
            for (int ntp = 0; ntp < 2; ++ntp) {
                int n = wn * 32 + ntp * 16 + (seg >> 1) * 8 + lrow;
                int kb = kt * 32 + (seg & 1) * 16;
                uint32_t sw = SWZ((uint32_t)(n * 128 + kb));
                ldmx4(Bhf[ntp], st + GS_BHI + sw);
                ldmx4(Blf[ntp], st + GS_BLO + sw);
            }
            #pragma unroll
            for (int mt = 0; mt < 2; ++mt)
                #pragma unroll
                for (int ntp = 0; ntp < 2; ++ntp)
                    #pragma unroll
                    for (int sub = 0; sub < 2; ++sub) {
                        int nj = ntp * 2 + sub;
                        mma_f16(acc[mt][nj], Af[mt], &Bhf[ntp][sub * 2]);
                        mma_f16(acc[mt][nj], Af[mt], &Blf[ntp][sub * 2]);
                    }
        }
        __syncthreads();
    }

    #pragma unroll
    for (int mt = 0; mt < 2; ++mt) {
        #pragma unroll
        for (int rp = 0; rp < 2; ++rp) {
            int row = rowBase + wm * 32 + mt * 16 + (lane >> 2) + rp * 8;
            if (row < NN) {
                float dv = g_dinv[row], rd = g_rdinv[row];
                #pragma unroll
                for (int nj = 0; nj < 4; ++nj) {
                    int col = wn * 32 + nj * 8 + (lane & 3) * 2;
                    float bz0 = s_bias[col], bz1 = s_bias[col + 1];
                    float p0 = fmaxf(fmaf(acc[mt][nj][rp * 2 + 0], rd, bz0), 0.f) * dv;
                    float p1 = fmaxf(fmaf(acc[mt][nj][rp * 2 + 1], rd, bz1), 0.f) * dv;
                    *(uint32_t*)(outp + (size_t)row * FH + col) = f2h2(p0, p1);
                }
            }
        }
    }
}

// ======================= final layer: mma GEMM, N padded to 64 (exact R13) ======
#define GF_A   0
#define GF_BHI 16384
#define GF_BLO 24576
#define GF_ST  32768
#define GF_SMEM_SZ (2 * GF_ST)

__global__ void __launch_bounds__(256, 3) k_gemm_final(
    const __half* __restrict__ x0,
    const float* __restrict__ bias,
    float* __restrict__ out) {
    extern __shared__ char smem_raw[];
    __shared__ float s_bias[64];
    uint32_t sb0 = smem_u32(smem_raw);
    uint32_t sb = (sb0 + 1023u) & ~1023u;

    const int tid = threadIdx.x, lane = tid & 31, wid = tid >> 5;
    const int wm = wid >> 1, wn = wid & 1;
    const int rowBase = blockIdx.x * 128;
    if (tid < 64) s_bias[tid] = (tid < FO) ? bias[tid] : 0.f;
    __syncthreads();

    const __half* Ap[3] = {x0, g_F1, g_F2};

    float acc[2][4][4];
    #pragma unroll
    for (int a = 0; a < 2; ++a)
        #pragma unroll
        for (int b = 0; b < 4; ++b)
            #pragma unroll
            for (int c = 0; c < 4; ++c) acc[a][b][c] = 0.f;

    const int lrow = lane & 7, seg = lane >> 3;

    auto load_chunk = [&](uint32_t st, int kc) {
        const int coff = (kc & 1) * 64;
        const __half* __restrict__ ap = Ap[kc >> 1];
        #pragma unroll
        for (int t = 0; t < 4; ++t) {
            int idx = tid + t * 256;
            int r = idx >> 3, j = idx & 7;
            int row = rowBase + r;
            bool ok = row < NN;
            int rowc = ok ? row : (NN - 1);
            uint32_t sw = SWZ((uint32_t)(r * 128 + j * 16));
            cpa16(st + GF_A + sw, ap + (size_t)rowc * FH + coff + j * 8, ok);
        }
        #pragma unroll
        for (int t = 0; t < 2; ++t) {
            int idx = tid + t * 256;
            int n = idx >> 3, j = idx & 7;
            uint32_t sw = SWZ((uint32_t)(n * 128 + j * 16));
            cpa16(st + GF_BHI + sw, g_WFh + (size_t)n * 384 + kc * 64 + j * 8, true);
            cpa16(st + GF_BLO + sw, g_WFl + (size_t)n * 384 + kc * 64 + j * 8, true);
        }
    };

    load_chunk(sb, 0);
    CP_COMMIT();

    #pragma unroll 1
    for (int kc = 0; kc < 6; ++kc) {
        if (kc < 5) {
            load_chunk(sb + (((kc + 1) & 1) ? GF_ST : 0), kc + 1);
            CP_COMMIT();
            CP_WAIT(1);
        } else {
            CP_WAIT(0);
        }
        __syncthreads();

        const uint32_t st = sb + ((kc & 1) ? GF_ST : 0);
        #pragma unroll
        for (int kt = 0; kt < 4; ++kt) {
            uint32_t Af[2][4], Bhf[2][4], Blf[2][4];
            #pragma unroll
            for (int mt = 0; mt < 2; ++mt) {
                int m = wm * 32 + mt * 16 + (seg & 1) * 8 + lrow;
                int kb = kt * 32 + (seg >> 1) * 16;
                uint32_t sw = SWZ((uint32_t)(m * 128 + kb));
                ldmx4(Af[mt], st + GF_A + sw);
            }
            #pragma unroll
            for (int ntp = 0; ntp < 2; ++ntp) {
                int n = wn * 32 + ntp * 16 + (seg >> 1) * 8 + lrow;
                int kb = kt * 32 + (seg & 1) * 16;
                uint32_t sw = SWZ((uint32_t)(n * 128 + kb));
                ldmx4(Bhf[ntp], st + GF_BHI + sw);
                ldmx4(Blf[ntp], st + GF_BLO + sw);
            }
            #pragma unroll
            for (int mt = 0; mt < 2; ++mt)
                #pragma unroll
                for (int ntp = 0; ntp < 2; ++ntp)
                    #pragma unroll
                    for (int sub = 0; sub < 2; ++sub) {
                        int nj = ntp * 2 + sub;
                        mma_f16(acc[mt][nj], Af[mt], &Bhf[ntp][sub * 2]);
                        mma_f16(acc[mt][nj], Af[mt], &Blf[ntp][sub * 2]);
                    }
        }
        __syncthreads();
    }

    #pragma unroll
    for (int mt = 0; mt < 2; ++mt) {
        #pragma unroll
        for (int rp = 0; rp < 2; ++rp) {
            int row = rowBase + wm * 32 + mt * 16 + (lane >> 2) + rp * 8;
            if (row < NN) {
                float rd = g_rdinv[row];
                #pragma unroll
                for (int nj = 0; nj < 4; ++nj) {
                    int col = wn * 32 + nj * 8 + (lane & 3) * 2;
                    if (col < FO) {
                        float bz0 = s_bias[col], bz1 = s_bias[col + 1];
                        float p0 = fmaxf(fmaf(acc[mt][nj][rp * 2 + 0], rd, bz0), 0.f);
                        float p1 = fmaxf(fmaf(acc[mt][nj][rp * 2 + 1], rd, bz1), 0.f);
                        *(float2*)(out + (size_t)row * FO + col) = make_float2(p0, p1);
                    }
                }
            }
        }
    }
}

// ======================= host launcher =======================
extern "C" void kernel_launch(void* const* d_in, const int* in_sizes, int n_in,
                              void* d_out, int out_size) {
    const float* feat = (const float*)d_in[0];
    const int*   src  = (const int*)d_in[1];
    const int*   dst  = (const int*)d_in[2];
    const float* W0   = (const float*)d_in[3];
    const float* b0   = (const float*)d_in[4];
    const float* Wh_  = (const float*)d_in[5];
    const float* bh   = (const float*)d_in[6];
    const float* Wl_  = (const float*)d_in[7];
    const float* bl   = (const float*)d_in[8];
    float* out = (float*)d_out;

    __half *F0, *F1, *F2, *Wh, *Wl;
    int* degp;
    cudaGetSymbolAddress((void**)&F0, g_F0);
    cudaGetSymbolAddress((void**)&F1, g_F1);
    cudaGetSymbolAddress((void**)&F2, g_F2);
    cudaGetSymbolAddress((void**)&Wh, g_Wh);
    cudaGetSymbolAddress((void**)&Wl, g_Wl);
    cudaGetSymbolAddress((void**)&degp, g_deg);

    cudaFuncSetAttribute(k_gemm_mma, cudaFuncAttributeMaxDynamicSharedMemorySize,
                         GM_SMEM_SZ + 1024);
    cudaFuncSetAttribute(k_gemm_final, cudaFuncAttributeMaxDynamicSharedMemorySize,
                         GF_SMEM_SZ + 1024);

    const int TPB = 256;
    const int nodeBlocks = (NN + TPB - 1) / TPB;
    const int edgeBlocks = (NE + TPB - 1) / TPB;
    const int scanBlocks = (NN + 1023) / 1024;   // 98

    // preprocessing
    cudaMemsetAsync(degp, 0, NN * sizeof(int));
    k_hist<<<edgeBlocks, TPB>>>(dst);
    k_scanA<<<scanBlocks, 1024>>>();
    k_scanB<<<1, 128>>>(scanBlocks);
    k_scanC<<<nodeBlocks, TPB>>>();
    k_scatter<<<edgeBlocks, TPB>>>(src, dst);

    // merged input conversion (featsplit | prep_w | prep_wf)
    k_prep<<<FS_BLK + PW_BLK + PF_BLK, TPB>>>(feat, W0, Wh_, Wl_);

    const size_t SL = (size_t)NN * FH;
    const int spmmBlocks = (NN * 32 + TPB - 1) / TPB;
    const int tileBlocks = (NN + 127) / 128;

    int cur = 0;
    for (int l = 0; l < 7; ++l) {
        const __half* F0c = F0 + (size_t)cur * SL;
        k_spmm<1><<<spmmBlocks, TPB>>>(F0c, nullptr, F1);
        k_spmm<2><<<spmmBlocks, TPB>>>(F1, F0c, F2);
        if (l < 6) {
            const float* bias = (l == 0) ? b0 : (bh + (size_t)(l - 1) * 128);
            int nxt = 1 - cur;
            k_gemm_mma<<<tileBlocks, 512, GM_SMEM_SZ + 1024>>>(
                F0c, bias,
                Wh + (size_t)l * 128 * 384, Wl + (size_t)l * 128 * 384,
                F0 + (size_t)nxt * SL);
            cur = nxt;
        } else {
            k_gemm_final<<<tileBlocks, 256, GF_SMEM_SZ + 1024>>>(F0c, bl, out);
        }
    }
}